// round 2
// baseline (speedup 1.0000x reference)
#include <cuda_runtime.h>
#include <cstdint>

// Problem constants (from reference)
//   x: (B=4, D+C=105, FH=32, FW=88) fp32
//   out: (B=4, C=64, NZ=200, NX=200) fp32 = 10,240,000 elems
#define DD   41
#define CCH  64
#define FH_  32
#define FW_  88
#define B_   4
#define NX0_ 200
#define NZ_  200

// 3x3 inverse via adjugate with correctly-rounded divisions.
// Bit-identical to LAPACK LU for these matrices; __fdiv_rn guards against
// fast-math build flags. DO NOT change (bin-boundary sensitivity).
__device__ __forceinline__ void inv3(const float* m, float* o) {
    float a = m[0], b = m[1], c = m[2];
    float d = m[3], e = m[4], f = m[5];
    float g = m[6], h = m[7], i = m[8];
    float c00 = e * i - f * h;
    float c01 = f * g - d * i;
    float c02 = d * h - e * g;
    float det = a * c00 + b * c01 + c * c02;
    o[0] = __fdiv_rn(c00, det);
    o[1] = __fdiv_rn(c * h - b * i, det);
    o[2] = __fdiv_rn(b * f - c * e, det);
    o[3] = __fdiv_rn(c01, det);
    o[4] = __fdiv_rn(a * i - c * g, det);
    o[5] = __fdiv_rn(c * d - a * f, det);
    o[6] = __fdiv_rn(c02, det);
    o[7] = __fdiv_rn(b * g - a * h, det);
    o[8] = __fdiv_rn(a * e - b * d, det);
}

// ---------------------------------------------------------------------------
// Main kernel. One block per (w, b). 512 threads = 16 warps.
//  Phase 1: load logits[41][32] + featT[32][64] into smem (coop, 512 thr)
//  Phase 2: softmax over D per pixel column h (16 partial groups)
//  Phase 3: per-(d,h) geometry -> bin + kept; h-uniformity check per d
//  Phase 4: warp = (d-group, channel-half), lane = channel:
//           v[c] = sum_h w[d][h]*feat[h][c] (4 accumulators), ONE atomic/ch
// ---------------------------------------------------------------------------
__global__ __launch_bounds__(512) void lss_main(
    const float* __restrict__ x,
    const float* __restrict__ intrins,
    const float* __restrict__ rots,
    const float* __restrict__ trans,
    float* __restrict__ out)
{
    __shared__ float wts[DD][FH_];      // logits -> exp -> masked weights
    __shared__ float featT[FH_][CCH];   // feat transposed: [h][c]
    __shared__ float pmax[16][FH_];
    __shared__ float psum[16][FH_];
    __shared__ float fullmax[FH_];
    __shared__ float fsum[FH_];
    __shared__ int   binsp[DD];
    __shared__ int   flags[DD];         // 0 = no kept, 1 = uniform, 2 = mixed
    __shared__ int   binh[DD][FH_];
    __shared__ float iR[9], iK[9], tv[3];

    const int w    = blockIdx.x;
    const int b    = blockIdx.y;
    const int tid  = threadIdx.x;
    const int lane = tid & 31;
    const int wg   = tid >> 5;          // 0..15

    if (tid == 0) {
        float mr[9], mk[9];
#pragma unroll
        for (int k = 0; k < 9; k++) { mr[k] = rots[b * 9 + k]; mk[k] = intrins[b * 9 + k]; }
        inv3(mr, iR);
        inv3(mk, iK);
        tv[0] = trans[b * 3 + 0]; tv[1] = trans[b * 3 + 1]; tv[2] = trans[b * 3 + 2];
    }

    // Phase 1: cooperative load of this (b, w) column: 105 channels x 32 rows
    const float* xb = x + (size_t)b * (105 * FH_ * FW_) + w;
#pragma unroll 7
    for (int i = tid; i < 105 * FH_; i += 512) {
        int ch = i >> 5, h = i & 31;
        float v = xb[(ch * FH_ + h) * FW_];
        if (ch < DD) wts[ch][h] = v;
        else         featT[h][ch - DD] = v;
    }
    __syncthreads();

    // Phase 2: softmax over d per h. Group g (=wg) covers d = g, g+16, g+32.
    {
        float pm = -3.402823466e38f;
        for (int d = wg; d < DD; d += 16) pm = fmaxf(pm, wts[d][lane]);
        pmax[wg][lane] = pm;
    }
    __syncthreads();
    if (tid < 32) {
        float m = pmax[0][lane];
#pragma unroll
        for (int g = 1; g < 16; g++) m = fmaxf(m, pmax[g][lane]);
        fullmax[lane] = m;
    }
    __syncthreads();
    {
        float m = fullmax[lane];
        float ps = 0.f;
        for (int d = wg; d < DD; d += 16) {
            float e = __expf(wts[d][lane] - m);
            wts[d][lane] = e;
            ps += e;
        }
        psum[wg][lane] = ps;
    }
    __syncthreads();
    if (tid < 32) {
        float s = psum[0][lane];
#pragma unroll
        for (int g = 1; g < 16; g++) s += psum[g][lane];
        fsum[lane] = s;
    }
    __syncthreads();

    // Phase 3: geometry. warp wg handles d = wg, wg+16, wg+32; lane = h.
    {
        // frustum (replicating jnp.linspace: i * fl(step))
        const float xs = (float)w    * (703.0f / 87.0f);
        const float ys = (float)lane * (255.0f / 31.0f);
        const float r00 = iR[0], r01 = iR[1], r02 = iR[2];
        const float r10 = iR[3], r11 = iR[4], r12 = iR[5];
        const float r20 = iR[6], r21 = iR[7], r22 = iR[8];
        const float k00 = iK[0], k01 = iK[1], k02 = iK[2];
        const float k10 = iK[3], k11 = iK[4], k12 = iK[5];
        const float k20 = iK[6], k21 = iK[7], k22 = iK[8];
        const float t0 = tv[0], t1 = tv[1], t2 = tv[2];
        const float p0 = xs - t0, p1 = ys - t1;
        const float rinv = __frcp_rn(fsum[lane]);

        for (int d = wg; d < DD; d += 16) {
            float p2 = (4.0f + (float)d) - t2;
            // q = invR @ p
            float q0 = __fmaf_rn(r00, p0, __fmaf_rn(r01, p1, r02 * p2));
            float q1 = __fmaf_rn(r10, p0, __fmaf_rn(r11, p1, r12 * p2));
            float q2 = __fmaf_rn(r20, p0, __fmaf_rn(r21, p1, r22 * p2));
            // s = (qx*qz, qy*qz, qz)
            float s0 = q0 * q2, s1 = q1 * q2, s2 = q2;
            // g = invK @ s
            float g0 = __fmaf_rn(k00, s0, __fmaf_rn(k01, s1, k02 * s2));
            float g1 = __fmaf_rn(k10, s0, __fmaf_rn(k11, s1, k12 * s2));
            float g2 = __fmaf_rn(k20, s0, __fmaf_rn(k21, s1, k22 * s2));
            // coords: truncation toward zero matches astype(int32)
            int c0 = (int)((g0 + 50.0f) / 0.5f);
            int c1 = (int)((g1 + 10.0f) / 20.0f);
            int c2 = (int)(g2 / 0.25f);
            bool kept = (c0 >= 0) & (c0 < NX0_) & (c1 >= 0) & (c1 < 1) &
                        (c2 >= 0) & (c2 < NZ_);
            int sp = c2 * NX0_ + c0;
            binh[d][lane] = sp;
            float wv = kept ? wts[d][lane] * rinv : 0.0f;
            wts[d][lane] = wv;

            unsigned km = __ballot_sync(0xffffffffu, kept);
            int fl = 0;
            if (km) {
                int src = __ffs(km) - 1;
                int lsp = __shfl_sync(0xffffffffu, sp, src);
                bool ok = (!kept) || (sp == lsp);
                fl = __all_sync(0xffffffffu, ok) ? 1 : 2;
                if (lane == 0) binsp[d] = lsp;
            }
            if (lane == 0) flags[d] = fl;
        }
    }
    __syncthreads();

    // Phase 4: matvec + scatter.
    // warp wg: channel-half ci = wg&1, d-group dg = wg>>1 (8 groups);
    // lane owns channel c = ci*32 + lane.
    {
        const int c  = ((wg & 1) << 5) + lane;
        const int dg = wg >> 1;

        float* ob = out + ((size_t)b * CCH + c) * (NZ_ * NX0_);
        for (int d = dg; d < DD; d += 8) {
            int fl = flags[d];
            if (fl == 0) continue;
            if (fl == 1) {
                float a0 = 0.f, a1 = 0.f, a2 = 0.f, a3 = 0.f;
#pragma unroll
                for (int h = 0; h < FH_; h += 4) {
                    a0 = __fmaf_rn(wts[d][h + 0], featT[h + 0][c], a0);
                    a1 = __fmaf_rn(wts[d][h + 1], featT[h + 1][c], a1);
                    a2 = __fmaf_rn(wts[d][h + 2], featT[h + 2][c], a2);
                    a3 = __fmaf_rn(wts[d][h + 3], featT[h + 3][c], a3);
                }
                atomicAdd(ob + binsp[d], (a0 + a1) + (a2 + a3));
            } else {
                // generic fallback: per-h scatter
                for (int h = 0; h < FH_; h++) {
                    float wv = wts[d][h];
                    if (wv != 0.f) atomicAdd(ob + binh[d][h], wv * featT[h][c]);
                }
            }
        }
    }
}

// ---------------------------------------------------------------------------
extern "C" void kernel_launch(void* const* d_in, const int* in_sizes, int n_in,
                              void* d_out, int out_size) {
    const float* x       = (const float*)d_in[0];
    const float* intrins = (const float*)d_in[1];
    const float* rots    = (const float*)d_in[2];
    const float* trans   = (const float*)d_in[3];
    float* out = (float*)d_out;

    // zero the accumulator output (capturable memset node)
    cudaMemsetAsync(out, 0, (size_t)out_size * sizeof(float));

    dim3 grid(FW_, B_);
    lss_main<<<grid, 512>>>(x, intrins, rots, trans, out);
}